// round 15
// baseline (speedup 1.0000x reference)
#include <cuda_runtime.h>
#include <math.h>
#include <stdint.h>

// Problem shapes (fixed by the dataset)
#define B_ROWS 16384
#define DK     512
#define NKEYS  4096
#define DV     512
#define NH     32
#define TAU_MIN 0.1f
#define TAU_MAX 5.0f
#define EPSF    1e-8f

// Scratch (never passed from host — selector/sentinel resolution in device code)
__device__ float g_logits[(size_t)B_ROWS * NKEYS];   // logits / attn scratch
__device__ float g_q [(size_t)B_ROWS * DK];          // tf32-rounded, k-permuted Q
__device__ float g_k [(size_t)NKEYS  * DK];          // tf32-rounded, k-permuted keys
__device__ float g_vt[(size_t)DV * NKEYS];           // tf32-rounded, k-permuted V^T

// k-permutation within a 16 block: [0,4,1,5,2,6,3,7, 8,12,9,13,10,14,11,15]
__device__ __forceinline__ int permk(int k) {
    return (k & 8) | ((k & 3) << 1) | ((k >> 2) & 1);
}

// ---------------------------------------------------------------------------
// helpers
// ---------------------------------------------------------------------------
__device__ __forceinline__ float round_tf32(float v) {
    uint32_t r;
    asm("cvt.rna.tf32.f32 %0, %1;" : "=r"(r) : "f"(v));
    return __uint_as_float(r);
}
__device__ __forceinline__ void mma_tf32(float* c, uint32_t a0, uint32_t a1,
                                         uint32_t a2, uint32_t a3,
                                         uint32_t b0, uint32_t b1)
{
    asm volatile(
        "mma.sync.aligned.m16n8k8.row.col.f32.tf32.tf32.f32 "
        "{%0,%1,%2,%3}, {%4,%5,%6,%7}, {%8,%9}, {%0,%1,%2,%3};"
        : "+f"(c[0]), "+f"(c[1]), "+f"(c[2]), "+f"(c[3])
        : "r"(a0), "r"(a1), "r"(a2), "r"(a3), "r"(b0), "r"(b1));
}
__device__ __forceinline__ void cp_async16(uint32_t saddr, const void* gptr) {
    asm volatile("cp.async.ca.shared.global [%0], [%1], 16;" :: "r"(saddr), "l"(gptr));
}
#define CP_COMMIT() asm volatile("cp.async.commit_group;" ::: "memory")
#define CP_WAIT1()  asm volatile("cp.async.wait_group 1;" ::: "memory")

// ---------------------------------------------------------------------------
// tf32 mma GEMM, 3-stage cp.async pipeline, 3 CTAs/SM (occupancy experiment).
// C[M,N] = alpha * A[M,K] @ B[N,K]^T
// B always k-permuted (g_k / g_vt). PERM_A: A k-permuted (GEMM1) or standard
// row-major (GEMM2 attn). K compile-time -> immediate address strides.
// sel==1: A=g_q, B=g_k, C=g_logits. sel==2: B=g_vt, A==nullptr -> g_logits.
// ---------------------------------------------------------------------------
#define BK 16
#define LDSW 20                     // 16 data + 4 pad words
#define STAGE_W (128 * LDSW)
#define STAGES 3
#define GEMM_SMEM (2 * STAGES * STAGE_W * 4)   // 61440 B -> 3 CTAs/SM

template <int PERM_A, int K>
__global__ __launch_bounds__(256, 3) void mma_gemm_kernel(
    const float* __restrict__ A, float* __restrict__ C,
    int ldc, float alpha, int sel)
{
    const float* Bm;
    if (sel == 1) { A = g_q; Bm = g_k; C = g_logits; }
    else          { Bm = g_vt; if (A == nullptr) A = g_logits; }

    extern __shared__ float smem[];
    float* As = smem;
    float* Bs = smem + STAGES * STAGE_W;
    const uint32_t sA = (uint32_t)__cvta_generic_to_shared(As);
    const uint32_t sB = (uint32_t)__cvta_generic_to_shared(Bs);

    const int tid  = threadIdx.x;
    const int wid  = tid >> 5;
    const int lane = tid & 31;
    const int gid  = lane >> 2;
    const int tig  = lane & 3;
    const int m0w  = (wid >> 1) * 32;
    const int n0w  = (wid & 1) * 64;
    const int bm0  = blockIdx.y * 128;
    const int bn0  = blockIdx.x * 128;

    const int grow = tid >> 2;            // 0..63
    const int gkc  = (tid & 3) * 4;       // 0,4,8,12

    const float* Ar0 = A  + (size_t)(bm0 + grow) * K + gkc;
    const float* Br0 = Bm + (size_t)(bn0 + grow) * K + gkc;
    const uint32_t so0 = (uint32_t)(grow * LDSW + gkc) * 4;
    const uint32_t so1 = (uint32_t)((grow + 64) * LDSW + gkc) * 4;

    float acc[2][8][4];
#pragma unroll
    for (int mi = 0; mi < 2; mi++)
#pragma unroll
        for (int ni = 0; ni < 8; ni++)
#pragma unroll
            for (int c = 0; c < 4; c++) acc[mi][ni][c] = 0.f;

    const int niter = K / BK;

    // prologue: stages 0..STAGES-2 (2 groups)
#pragma unroll
    for (int s = 0; s < STAGES - 1; ++s) {
        const int k0 = s * BK;
        const uint32_t ob = (uint32_t)(s * STAGE_W) * 4;
        cp_async16(sA + ob + so0, Ar0 + k0);
        cp_async16(sA + ob + so1, Ar0 + (size_t)64 * K + k0);
        cp_async16(sB + ob + so0, Br0 + k0);
        cp_async16(sB + ob + so1, Br0 + (size_t)64 * K + k0);
        CP_COMMIT();
    }

    for (int it = 0; it < niter; ++it) {
        CP_WAIT1();
        __syncthreads();

        const int nt = it + STAGES - 1;
        if (nt < niter) {
            const int k0 = nt * BK;
            const uint32_t ob = (uint32_t)((nt % STAGES) * STAGE_W) * 4;
            cp_async16(sA + ob + so0, Ar0 + k0);
            cp_async16(sA + ob + so1, Ar0 + (size_t)64 * K + k0);
            cp_async16(sB + ob + so0, Br0 + k0);
            cp_async16(sB + ob + so1, Br0 + (size_t)64 * K + k0);
        }
        CP_COMMIT();

        const uint32_t* Ab = (const uint32_t*)(As + (it % STAGES) * STAGE_W);
        const uint32_t* Bb = (const uint32_t*)(Bs + (it % STAGES) * STAGE_W);
#pragma unroll
        for (int ks = 0; ks < 2; ks++) {
            uint32_t a0[2], a1[2], a2[2], a3[2];
#pragma unroll
            for (int mi = 0; mi < 2; mi++) {
                const int r = m0w + mi * 16 + gid;
                if (PERM_A) {
                    uint2 lo = *(const uint2*)&Ab[r * LDSW + ks * 8 + 2 * tig];
                    uint2 hi = *(const uint2*)&Ab[(r + 8) * LDSW + ks * 8 + 2 * tig];
                    a0[mi] = lo.x; a2[mi] = lo.y;
                    a1[mi] = hi.x; a3[mi] = hi.y;
                } else {
                    const int kk = ks * 8 + tig;
                    a0[mi] = Ab[r * LDSW + kk];
                    a1[mi] = Ab[(r + 8) * LDSW + kk];
                    a2[mi] = Ab[r * LDSW + kk + 4];
                    a3[mi] = Ab[(r + 8) * LDSW + kk + 4];
                }
            }
#pragma unroll
            for (int ni = 0; ni < 8; ni++) {
                const int c = n0w + ni * 8 + gid;
                uint2 b = *(const uint2*)&Bb[c * LDSW + ks * 8 + 2 * tig];
#pragma unroll
                for (int mi = 0; mi < 2; mi++)
                    mma_tf32(acc[mi][ni], a0[mi], a1[mi], a2[mi], a3[mi], b.x, b.y);
            }
        }
    }

    // epilogue
#pragma unroll
    for (int mi = 0; mi < 2; mi++) {
        const int row0 = bm0 + m0w + mi * 16 + gid;
#pragma unroll
        for (int ni = 0; ni < 8; ni++) {
            const int col = bn0 + n0w + ni * 8 + tig * 2;
            float2 v0 = make_float2(alpha * acc[mi][ni][0], alpha * acc[mi][ni][1]);
            float2 v1 = make_float2(alpha * acc[mi][ni][2], alpha * acc[mi][ni][3]);
            *(float2*)&C[(size_t)row0 * ldc + col]       = v0;
            *(float2*)&C[(size_t)(row0 + 8) * ldc + col] = v1;
        }
    }
}

// ---------------------------------------------------------------------------
// Pre-round Q/keys to tf32 grid AND k-permute within 16-blocks.
// ---------------------------------------------------------------------------
__device__ __forceinline__ void permute_block16(const float4* in, float4* out)
{
    float4 i0 = in[0], i1 = in[1], i2 = in[2], i3 = in[3];
    float4 o0 = make_float4(i0.x, i1.x, i0.y, i1.y);
    float4 o1 = make_float4(i0.z, i1.z, i0.w, i1.w);
    float4 o2 = make_float4(i2.x, i3.x, i2.y, i3.y);
    float4 o3 = make_float4(i2.z, i3.z, i2.w, i3.w);
    o0.x = round_tf32(o0.x); o0.y = round_tf32(o0.y); o0.z = round_tf32(o0.z); o0.w = round_tf32(o0.w);
    o1.x = round_tf32(o1.x); o1.y = round_tf32(o1.y); o1.z = round_tf32(o1.z); o1.w = round_tf32(o1.w);
    o2.x = round_tf32(o2.x); o2.y = round_tf32(o2.y); o2.z = round_tf32(o2.z); o2.w = round_tf32(o2.w);
    o3.x = round_tf32(o3.x); o3.y = round_tf32(o3.y); o3.z = round_tf32(o3.z); o3.w = round_tf32(o3.w);
    out[0] = o0; out[1] = o1; out[2] = o2; out[3] = o3;
}

__global__ void preround_kernel(const float* __restrict__ q,
                                const float* __restrict__ keys)
{
    const size_t nq16 = (size_t)B_ROWS * DK / 16;
    const size_t nk16 = (size_t)NKEYS * DK / 16;
    const size_t stride = (size_t)gridDim.x * blockDim.x;
    for (size_t b = blockIdx.x * (size_t)blockDim.x + threadIdx.x;
         b < nq16; b += stride)
        permute_block16((const float4*)(q + b * 16), (float4*)(g_q + b * 16));
    for (size_t b = blockIdx.x * (size_t)blockDim.x + threadIdx.x;
         b < nk16; b += stride)
        permute_block16((const float4*)(keys + b * 16), (float4*)(g_k + b * 16));
}

// ---------------------------------------------------------------------------
// V transpose with tf32 rounding + k-permute along the NKEYS dim:
// g_vt[d][perm(n)] = round(V[n][d])
// ---------------------------------------------------------------------------
__global__ void transpose_v_kernel(const float* __restrict__ V)
{
    __shared__ float t[32][33];
    const int n0 = blockIdx.x * 32;
    const int d0 = blockIdx.y * 32;
    const int x = threadIdx.x, y = threadIdx.y;
#pragma unroll
    for (int yy = y; yy < 32; yy += 8)
        t[yy][x] = V[(size_t)(n0 + yy) * DV + d0 + x];
    __syncthreads();
    const int xp = (x & ~15) | permk(x & 15);
#pragma unroll
    for (int yy = y; yy < 32; yy += 8)
        g_vt[(size_t)(d0 + yy) * NKEYS + n0 + xp] = round_tf32(t[x][yy]);
}

// ---------------------------------------------------------------------------
// FUSED per-row pass (identical to R12-passing version)
// ---------------------------------------------------------------------------
__device__ __forceinline__ void mzs_combine(float& m, float& Z, float& S,
                                            float m2, float Z2, float S2)
{
    float mn = fmaxf(m, m2);
    float e1 = __expf(m - mn);
    float e2 = __expf(m2 - mn);
    Z = Z * e1 + Z2 * e2;
    S = S * e1 + S2 * e2;
    m = mn;
}

__global__ __launch_bounds__(256) void fused_row_kernel(
    const float* __restrict__ w1, const float* __restrict__ b1,
    const float* __restrict__ w2, const float* __restrict__ b2,
    float* __restrict__ attn_out, float* __restrict__ ent_out,
    float* __restrict__ tau_out)
{
    __shared__ float sw[NKEYS];
    __shared__ float sred[8];
    __shared__ float sbc[2];
    __shared__ float smr[8], szr[8], ssr[8];

    if (attn_out == nullptr) attn_out = g_logits;
    const int row = blockIdx.x;
    const int tid = threadIdx.x;
    const float4* c4 = (const float4*)(g_logits + (size_t)row * NKEYS);
    float4* s4 = (float4*)sw;

    float m = -INFINITY, Z = 0.f, S = 0.f;
#pragma unroll
    for (int i = 0; i < 4; i++) {
        const int j = tid + i * 256;
        float4 v = c4[j];
        s4[j] = v;
        float f[4] = {v.x, v.y, v.z, v.w};
#pragma unroll
        for (int e = 0; e < 4; e++) {
            float l = f[e];
            if (l > m) {
                float sc = __expf(m - l);
                Z *= sc; S *= sc; m = l;
            }
            float ex = __expf(l - m);
            Z += ex;
            S += ex * l;
        }
    }
#pragma unroll
    for (int off = 16; off; off >>= 1) {
        float m2 = __shfl_down_sync(0xffffffffu, m, off);
        float Z2 = __shfl_down_sync(0xffffffffu, Z, off);
        float S2 = __shfl_down_sync(0xffffffffu, S, off);
        mzs_combine(m, Z, S, m2, Z2, S2);
    }
    const int wid = tid >> 5, lane = tid & 31;
    if (lane == 0) { smr[wid] = m; szr[wid] = Z; ssr[wid] = S; }
    __syncthreads();

    if (tid == 0) {
        m = smr[0]; Z = szr[0]; S = ssr[0];
#pragma unroll
        for (int w = 1; w < 8; w++) mzs_combine(m, Z, S, smr[w], szr[w], ssr[w]);

        float H = m + logf(Z) - S / Z - (float)NKEYS * EPSF;
        float max_entropy = logf((float)NKEYS);
        float e = H / (max_entropy + EPSF);
        e = fminf(fmaxf(e, 0.f), 1.f);

        float acc2 = b2[0];
#pragma unroll
        for (int h = 0; h < NH; h++) {
            float z1 = e * w1[h] + b1[h];
            float g  = 0.5f * z1 * (1.f + erff(z1 * 0.70710678118654752f));
            acc2 += g * w2[h];
        }
        float sc  = 1.f / (1.f + expf(-acc2));
        float tau = TAU_MIN + (TAU_MAX - TAU_MIN) * sc;

        if (ent_out) ent_out[row] = e;
        if (tau_out) tau_out[row] = tau;
        sbc[0] = m;
        sbc[1] = 1.f / (tau + EPSF);
    }
    __syncthreads();

    const float mm   = sbc[0];
    const float itau = sbc[1];
    float z = 0.f;
#pragma unroll
    for (int i = 0; i < 4; i++) {
        const int j = tid + i * 256;
        float4 v = s4[j];
        v.x = __expf((v.x - mm) * itau);
        v.y = __expf((v.y - mm) * itau);
        v.z = __expf((v.z - mm) * itau);
        v.w = __expf((v.w - mm) * itau);
        s4[j] = v;
        z += v.x + v.y + v.z + v.w;
    }
#pragma unroll
    for (int off = 16; off; off >>= 1)
        z += __shfl_down_sync(0xffffffffu, z, off);
    if (lane == 0) sred[wid] = z;
    __syncthreads();
    if (tid == 0) {
        float t = 0.f;
#pragma unroll
        for (int w = 0; w < 8; w++) t += sred[w];
        sred[0] = 1.f / t;
    }
    __syncthreads();
    const float invz = sred[0];

    float4* o4 = (float4*)(attn_out + (size_t)row * NKEYS);
#pragma unroll
    for (int i = 0; i < 4; i++) {
        const int j = tid + i * 256;
        float4 v = s4[j];
        v.x = round_tf32(v.x * invz);
        v.y = round_tf32(v.y * invz);
        v.z = round_tf32(v.z * invz);
        v.w = round_tf32(v.w * invz);
        o4[j] = v;
    }
}

// ---------------------------------------------------------------------------
extern "C" void kernel_launch(void* const* d_in, const int* in_sizes, int n_in,
                              void* d_out, int out_size)
{
    const float* q      = (const float*)d_in[0];
    const float* keys   = (const float*)d_in[1];
    const float* values = (const float*)d_in[2];
    const float* w1     = (const float*)d_in[3];
    const float* b1     = (const float*)d_in[4];
    const float* w2     = (const float*)d_in[5];
    const float* b2     = (const float*)d_in[6];
    float* out = (float*)d_out;

    const size_t sz_o    = (size_t)B_ROWS * DV;
    const size_t sz_attn = (size_t)B_ROWS * NKEYS;
    const size_t full_sz = sz_o + sz_attn + 2 * (size_t)B_ROWS;
    const bool full = ((size_t)out_size >= full_sz);

    float* out_o    = out;
    float* out_attn = full ? out + sz_o : nullptr;
    float* out_ent  = full ? out + sz_o + sz_attn : nullptr;
    float* out_tau  = full ? out_ent + B_ROWS : nullptr;

    const float base_scale = 0.044194173824159216f;          // 512^-0.5

    cudaFuncSetAttribute(mma_gemm_kernel<1, DK>,
                         cudaFuncAttributeMaxDynamicSharedMemorySize, GEMM_SMEM);
    cudaFuncSetAttribute(mma_gemm_kernel<0, NKEYS>,
                         cudaFuncAttributeMaxDynamicSharedMemorySize, GEMM_SMEM);

    // 0a) pre-round + k-permute Q, keys
    preround_kernel<<<1024, 256>>>(q, keys);
    // 0b) transpose + round + k-permute V -> g_vt
    transpose_v_kernel<<<dim3(NKEYS / 32, DV / 32), dim3(32, 8)>>>(values);

    // 1) scaled logits -> g_logits (both operands permuted)
    mma_gemm_kernel<1, DK><<<dim3(NKEYS / 128, B_ROWS / 128), 256, GEMM_SMEM>>>(
        nullptr, nullptr, NKEYS, base_scale, 1);

    // 2+3) fused entropy + tau + tau-softmax
    fused_row_kernel<<<B_ROWS, 256>>>(w1, b1, w2, b2, out_attn, out_ent, out_tau);

    // 4) output = attn @ V (A standard layout, B permuted)
    const float* attn_src = full ? out_attn : nullptr;
    mma_gemm_kernel<0, NKEYS><<<dim3(DV / 128, B_ROWS / 128), 256, GEMM_SMEM>>>(
        attn_src, out_o, DV, 1.0f, 2);
}

// round 16
// speedup vs baseline: 2.2951x; 2.2951x over previous
#include <cuda_runtime.h>
#include <cuda_fp16.h>
#include <math.h>
#include <stdint.h>

// Problem shapes (fixed by the dataset)
#define B_ROWS 16384
#define DK     512
#define NKEYS  4096
#define DV     512
#define NH     32
#define TAU_MIN 0.1f
#define TAU_MAX 5.0f
#define EPSF    1e-8f

// Scratch (never passed from host — selector resolution in device code)
__device__ float  g_logits[(size_t)B_ROWS * NKEYS];  // f32 logits
__device__ __half g_qh [(size_t)B_ROWS * DK];        // f16 Q
__device__ __half g_kh [(size_t)NKEYS  * DK];        // f16 keys
__device__ __half g_vth[(size_t)DV * NKEYS];         // f16 V^T
__device__ __half g_ah [(size_t)B_ROWS * NKEYS];     // f16 attn (GEMM2 A)

// ---------------------------------------------------------------------------
// helpers
// ---------------------------------------------------------------------------
__device__ __forceinline__ void mma_f16(float* c, uint32_t a0, uint32_t a1,
                                        uint32_t a2, uint32_t a3,
                                        uint32_t b0, uint32_t b1)
{
    asm volatile(
        "mma.sync.aligned.m16n8k16.row.col.f32.f16.f16.f32 "
        "{%0,%1,%2,%3}, {%4,%5,%6,%7}, {%8,%9}, {%0,%1,%2,%3};"
        : "+f"(c[0]), "+f"(c[1]), "+f"(c[2]), "+f"(c[3])
        : "r"(a0), "r"(a1), "r"(a2), "r"(a3), "r"(b0), "r"(b1));
}
__device__ __forceinline__ void cp_async16(uint32_t saddr, const void* gptr) {
    asm volatile("cp.async.ca.shared.global [%0], [%1], 16;" :: "r"(saddr), "l"(gptr));
}
#define CP_COMMIT() asm volatile("cp.async.commit_group;" ::: "memory")
#define CP_WAIT2()  asm volatile("cp.async.wait_group 2;" ::: "memory")

// ---------------------------------------------------------------------------
// f16 mma GEMM, 4-stage cp.async pipeline.
// C[M,N] = alpha * A[M,K] @ B[N,K]^T   (A, B f16 K-major; C f32)
// CTA tile 128x128, BK=32 (two k16 steps), 256 threads (8 warps 4x2),
// warp tile 32x64. Fragment/accumulator layout identical to the proven
// R10/R12 tf32 kernel with k-pairs packed into half2.
// sel==1: A=g_qh, B=g_kh, C=g_logits (GEMM1). sel==2: A=g_ah, B=g_vth.
// ---------------------------------------------------------------------------
#define BK 32
#define LDH 40                      // halves per smem row (32 data + 8 pad)
#define LDW (LDH / 2)               // 20 words per row; conflict-free banks
#define STAGE_H (128 * LDH)         // halves per stage per matrix
#define STAGES 4
#define GEMM_SMEM (2 * STAGES * STAGE_H * 2)   // 81920 B -> 2 CTAs/SM

__global__ __launch_bounds__(256, 2) void mma_gemm_f16_kernel(
    float* __restrict__ C, int K, int ldc, float alpha, int sel)
{
    const __half* A;
    const __half* Bm;
    if (sel == 1) { A = g_qh; Bm = g_kh; C = g_logits; }
    else          { A = g_ah; Bm = g_vth; }

    extern __shared__ __half smem[];
    __half* As = smem;
    __half* Bs = smem + STAGES * STAGE_H;
    const uint32_t sA = (uint32_t)__cvta_generic_to_shared(As);
    const uint32_t sB = (uint32_t)__cvta_generic_to_shared(Bs);

    const int tid  = threadIdx.x;
    const int wid  = tid >> 5;
    const int lane = tid & 31;
    const int gid  = lane >> 2;
    const int tig  = lane & 3;
    const int m0w  = (wid >> 1) * 32;
    const int n0w  = (wid & 1) * 64;
    const int bm0  = blockIdx.y * 128;
    const int bn0  = blockIdx.x * 128;

    // staging: 4 threads per row, 8 halves (16 B) each -> 32 k per row
    const int grow = tid >> 2;            // 0..63
    const int gkc  = (tid & 3) * 8;       // half offset 0,8,16,24

    const __half* Ar0 = A  + (size_t)(bm0 + grow) * K + gkc;
    const __half* Ar1 = Ar0 + (size_t)64 * K;
    const __half* Br0 = Bm + (size_t)(bn0 + grow) * K + gkc;
    const __half* Br1 = Br0 + (size_t)64 * K;
    const uint32_t so0 = (uint32_t)(grow * LDH + gkc) * 2;
    const uint32_t so1 = (uint32_t)((grow + 64) * LDH + gkc) * 2;

    float acc[2][8][4];
#pragma unroll
    for (int mi = 0; mi < 2; mi++)
#pragma unroll
        for (int ni = 0; ni < 8; ni++)
#pragma unroll
            for (int c = 0; c < 4; c++) acc[mi][ni][c] = 0.f;

    const int niter = K / BK;

    // prologue: stages 0..STAGES-2
#pragma unroll
    for (int s = 0; s < STAGES - 1; ++s) {
        if (s < niter) {
            const int k0 = s * BK;
            const uint32_t ob = (uint32_t)(s * STAGE_H) * 2;
            cp_async16(sA + ob + so0, Ar0 + k0);
            cp_async16(sA + ob + so1, Ar1 + k0);
            cp_async16(sB + ob + so0, Br0 + k0);
            cp_async16(sB + ob + so1, Br1 + k0);
        }
        CP_COMMIT();
    }

    for (int it = 0; it < niter; ++it) {
        CP_WAIT2();
        __syncthreads();

        const int nt = it + STAGES - 1;
        if (nt < niter) {
            const int k0 = nt * BK;
            const uint32_t ob = (uint32_t)((nt % STAGES) * STAGE_H) * 2;
            cp_async16(sA + ob + so0, Ar0 + k0);
            cp_async16(sA + ob + so1, Ar1 + k0);
            cp_async16(sB + ob + so0, Br0 + k0);
            cp_async16(sB + ob + so1, Br1 + k0);
        }
        CP_COMMIT();

        const uint32_t* Ab = (const uint32_t*)(As + (it % STAGES) * STAGE_H);
        const uint32_t* Bb = (const uint32_t*)(Bs + (it % STAGES) * STAGE_H);
#pragma unroll
        for (int ks = 0; ks < 2; ks++) {        // two k16 steps per BK=32
            const int kw = ks * 8 + tig;        // word col within row
            uint32_t a0[2], a1[2], a2[2], a3[2];
#pragma unroll
            for (int mi = 0; mi < 2; mi++) {
                const int r = m0w + mi * 16 + gid;
                a0[mi] = Ab[r * LDW + kw];            // (row r,   k 2tig..2tig+1)
                a1[mi] = Ab[(r + 8) * LDW + kw];      // (row r+8, same)
                a2[mi] = Ab[r * LDW + kw + 4];        // (row r,   k +8 pair)
                a3[mi] = Ab[(r + 8) * LDW + kw + 4];  // (row r+8, k +8 pair)
            }
#pragma unroll
            for (int ni = 0; ni < 8; ni++) {
                const int c = n0w + ni * 8 + gid;
                const uint32_t b0 = Bb[c * LDW + kw];
                const uint32_t b1 = Bb[c * LDW + kw + 4];
#pragma unroll
                for (int mi = 0; mi < 2; mi++)
                    mma_f16(acc[mi][ni], a0[mi], a1[mi], a2[mi], a3[mi], b0, b1);
            }
        }
    }

    // epilogue (identical layout to R10/R12)
#pragma unroll
    for (int mi = 0; mi < 2; mi++) {
        const int row0 = bm0 + m0w + mi * 16 + gid;
#pragma unroll
        for (int ni = 0; ni < 8; ni++) {
            const int col = bn0 + n0w + ni * 8 + tig * 2;
            float2 v0 = make_float2(alpha * acc[mi][ni][0], alpha * acc[mi][ni][1]);
            float2 v1 = make_float2(alpha * acc[mi][ni][2], alpha * acc[mi][ni][3]);
            *(float2*)&C[(size_t)row0 * ldc + col]       = v0;
            *(float2*)&C[(size_t)(row0 + 8) * ldc + col] = v1;
        }
    }
}

// ---------------------------------------------------------------------------
// Convert Q, keys to f16 (grid-stride; 8 floats -> 8 halves per thread step)
// ---------------------------------------------------------------------------
__global__ void to_half_kernel(const float* __restrict__ q,
                               const float* __restrict__ keys)
{
    const size_t nq8 = (size_t)B_ROWS * DK / 8;
    const size_t nk8 = (size_t)NKEYS * DK / 8;
    const size_t stride = (size_t)gridDim.x * blockDim.x;
    for (size_t i = blockIdx.x * (size_t)blockDim.x + threadIdx.x;
         i < nq8; i += stride) {
        float4 v0 = ((const float4*)q)[i * 2];
        float4 v1 = ((const float4*)q)[i * 2 + 1];
        __half2* o = (__half2*)(g_qh + i * 8);
        o[0] = __floats2half2_rn(v0.x, v0.y);
        o[1] = __floats2half2_rn(v0.z, v0.w);
        o[2] = __floats2half2_rn(v1.x, v1.y);
        o[3] = __floats2half2_rn(v1.z, v1.w);
    }
    for (size_t i = blockIdx.x * (size_t)blockDim.x + threadIdx.x;
         i < nk8; i += stride) {
        float4 v0 = ((const float4*)keys)[i * 2];
        float4 v1 = ((const float4*)keys)[i * 2 + 1];
        __half2* o = (__half2*)(g_kh + i * 8);
        o[0] = __floats2half2_rn(v0.x, v0.y);
        o[1] = __floats2half2_rn(v0.z, v0.w);
        o[2] = __floats2half2_rn(v1.x, v1.y);
        o[3] = __floats2half2_rn(v1.z, v1.w);
    }
}

// ---------------------------------------------------------------------------
// V transpose to f16: g_vth[d, n] = (half)V[n, d]
// ---------------------------------------------------------------------------
__global__ void transpose_v_kernel(const float* __restrict__ V)
{
    __shared__ float t[32][33];
    const int n0 = blockIdx.x * 32;
    const int d0 = blockIdx.y * 32;
    const int x = threadIdx.x, y = threadIdx.y;
#pragma unroll
    for (int yy = y; yy < 32; yy += 8)
        t[yy][x] = V[(size_t)(n0 + yy) * DV + d0 + x];
    __syncthreads();
#pragma unroll
    for (int yy = y; yy < 32; yy += 8)
        g_vth[(size_t)(d0 + yy) * NKEYS + n0 + x] = __float2half_rn(t[x][yy]);
}

// ---------------------------------------------------------------------------
// FUSED per-row pass: one logits read; entropy -> MLP -> tau -> tau-softmax.
// Writes attn f32 to output buffer AND f16 copy to g_ah (GEMM2 operand).
// ---------------------------------------------------------------------------
__device__ __forceinline__ void mzs_combine(float& m, float& Z, float& S,
                                            float m2, float Z2, float S2)
{
    float mn = fmaxf(m, m2);
    float e1 = __expf(m - mn);
    float e2 = __expf(m2 - mn);
    Z = Z * e1 + Z2 * e2;
    S = S * e1 + S2 * e2;
    m = mn;
}

__global__ __launch_bounds__(256) void fused_row_kernel(
    const float* __restrict__ w1, const float* __restrict__ b1,
    const float* __restrict__ w2, const float* __restrict__ b2,
    float* __restrict__ attn_out, float* __restrict__ ent_out,
    float* __restrict__ tau_out)
{
    __shared__ float sw[NKEYS];
    __shared__ float sred[8];
    __shared__ float sbc[2];
    __shared__ float smr[8], szr[8], ssr[8];

    if (attn_out == nullptr) attn_out = g_logits;
    const int row = blockIdx.x;
    const int tid = threadIdx.x;
    const float4* c4 = (const float4*)(g_logits + (size_t)row * NKEYS);
    float4* s4 = (float4*)sw;

    float m = -INFINITY, Z = 0.f, S = 0.f;
#pragma unroll
    for (int i = 0; i < 4; i++) {
        const int j = tid + i * 256;
        float4 v = c4[j];
        s4[j] = v;
        float f[4] = {v.x, v.y, v.z, v.w};
#pragma unroll
        for (int e = 0; e < 4; e++) {
            float l = f[e];
            if (l > m) {
                float sc = __expf(m - l);
                Z *= sc; S *= sc; m = l;
            }
            float ex = __expf(l - m);
            Z += ex;
            S += ex * l;
        }
    }
#pragma unroll
    for (int off = 16; off; off >>= 1) {
        float m2 = __shfl_down_sync(0xffffffffu, m, off);
        float Z2 = __shfl_down_sync(0xffffffffu, Z, off);
        float S2 = __shfl_down_sync(0xffffffffu, S, off);
        mzs_combine(m, Z, S, m2, Z2, S2);
    }
    const int wid = tid >> 5, lane = tid & 31;
    if (lane == 0) { smr[wid] = m; szr[wid] = Z; ssr[wid] = S; }
    __syncthreads();

    if (tid == 0) {
        m = smr[0]; Z = szr[0]; S = ssr[0];
#pragma unroll
        for (int w = 1; w < 8; w++) mzs_combine(m, Z, S, smr[w], szr[w], ssr[w]);

        float H = m + logf(Z) - S / Z - (float)NKEYS * EPSF;
        float max_entropy = logf((float)NKEYS);
        float e = H / (max_entropy + EPSF);
        e = fminf(fmaxf(e, 0.f), 1.f);

        float acc2 = b2[0];
#pragma unroll
        for (int h = 0; h < NH; h++) {
            float z1 = e * w1[h] + b1[h];
            float g  = 0.5f * z1 * (1.f + erff(z1 * 0.70710678118654752f));
            acc2 += g * w2[h];
        }
        float sc  = 1.f / (1.f + expf(-acc2));
        float tau = TAU_MIN + (TAU_MAX - TAU_MIN) * sc;

        if (ent_out) ent_out[row] = e;
        if (tau_out) tau_out[row] = tau;
        sbc[0] = m;
        sbc[1] = 1.f / (tau + EPSF);
    }
    __syncthreads();

    const float mm   = sbc[0];
    const float itau = sbc[1];
    float z = 0.f;
#pragma unroll
    for (int i = 0; i < 4; i++) {
        const int j = tid + i * 256;
        float4 v = s4[j];
        v.x = __expf((v.x - mm) * itau);
        v.y = __expf((v.y - mm) * itau);
        v.z = __expf((v.z - mm) * itau);
        v.w = __expf((v.w - mm) * itau);
        s4[j] = v;
        z += v.x + v.y + v.z + v.w;
    }
#pragma unroll
    for (int off = 16; off; off >>= 1)
        z += __shfl_down_sync(0xffffffffu, z, off);
    if (lane == 0) sred[wid] = z;
    __syncthreads();
    if (tid == 0) {
        float t = 0.f;
#pragma unroll
        for (int w = 0; w < 8; w++) t += sred[w];
        sred[0] = 1.f / t;
    }
    __syncthreads();
    const float invz = sred[0];

    float4*  o4 = (float4*)(attn_out + (size_t)row * NKEYS);
    __half2* h2 = (__half2*)(g_ah + (size_t)row * NKEYS);
#pragma unroll
    for (int i = 0; i < 4; i++) {
        const int j = tid + i * 256;
        float4 v = s4[j];
        v.x *= invz; v.y *= invz; v.z *= invz; v.w *= invz;
        o4[j] = v;                                  // f32 attn (output)
        h2[j * 2]     = __floats2half2_rn(v.x, v.y); // f16 attn (GEMM2 A)
        h2[j * 2 + 1] = __floats2half2_rn(v.z, v.w);
    }
}

// ---------------------------------------------------------------------------
extern "C" void kernel_launch(void* const* d_in, const int* in_sizes, int n_in,
                              void* d_out, int out_size)
{
    const float* q      = (const float*)d_in[0];
    const float* keys   = (const float*)d_in[1];
    const float* values = (const float*)d_in[2];
    const float* w1     = (const float*)d_in[3];
    const float* b1     = (const float*)d_in[4];
    const float* w2     = (const float*)d_in[5];
    const float* b2     = (const float*)d_in[6];
    float* out = (float*)d_out;

    const size_t sz_o    = (size_t)B_ROWS * DV;
    const size_t sz_attn = (size_t)B_ROWS * NKEYS;
    const size_t full_sz = sz_o + sz_attn + 2 * (size_t)B_ROWS;
    const bool full = ((size_t)out_size >= full_sz);

    float* out_o    = out;
    float* out_attn = full ? out + sz_o : nullptr;
    float* out_ent  = full ? out + sz_o + sz_attn : nullptr;
    float* out_tau  = full ? out_ent + B_ROWS : nullptr;

    const float base_scale = 0.044194173824159216f;          // 512^-0.5

    cudaFuncSetAttribute(mma_gemm_f16_kernel,
                         cudaFuncAttributeMaxDynamicSharedMemorySize, GEMM_SMEM);

    // 0a) Q, keys -> f16
    to_half_kernel<<<1024, 256>>>(q, keys);
    // 0b) V -> f16 transpose
    transpose_v_kernel<<<dim3(NKEYS / 32, DV / 32), dim3(32, 8)>>>(values);

    // 1) scaled logits -> g_logits (f16 mma)
    mma_gemm_f16_kernel<<<dim3(NKEYS / 128, B_ROWS / 128), 256, GEMM_SMEM>>>(
        nullptr, DK, NKEYS, base_scale, 1);

    // 2+3) fused entropy + tau + tau-softmax; writes f32 attn + f16 copy
    fused_row_kernel<<<B_ROWS, 256>>>(w1, b1, w2, b2, out_attn, out_ent, out_tau);

    // 4) output = attn @ V (f16 mma: A=g_ah, B=g_vth)
    mma_gemm_f16_kernel<<<dim3(DV / 128, B_ROWS / 128), 256, GEMM_SMEM>>>(
        out_o, NKEYS, DV, 1.0f, 2);
}